// round 2
// baseline (speedup 1.0000x reference)
#include <cuda_runtime.h>
#include <math.h>

// Problem constants
#define NCTA 128
#define TPB  256
#define KC   64
#define XST  68   // xs row stride in floats (odd multiple of float4 -> conflict-free)

// ---------------- device scratch (static, no allocation) ----------------
__device__ float g_Wr[4096 * 2048];        // reordered [encW0|encW1|decW0|decW1]
__device__ float g_h0[2 * 64 * 512];       // ping-pong layer0 h
__device__ float g_h1[2 * 64 * 512];       // ping-pong layer1 h
__device__ float g_c0[64 * 512];
__device__ float g_c1[64 * 512];
__device__ float g_en_last[64 * 512];
__device__ float g_dec_out[64 * 256 * 512];
__device__ unsigned g_bar;

__device__ __forceinline__ float sigmoidf_(float x) { return 1.0f / (1.0f + expf(-x)); }

// Grid-wide barrier: monotonically increasing counter, reset per launch by init kernel.
__device__ __forceinline__ void grid_bar(unsigned target) {
    __syncthreads();
    if (threadIdx.x == 0) {
        __threadfence();                 // release prior writes
        atomicAdd(&g_bar, 1u);
        unsigned v;
        do {
            asm volatile("ld.acquire.gpu.u32 %0, [%1];" : "=r"(v) : "l"(&g_bar));
        } while (v < target);
    }
    __syncthreads();
}

// Inner GEMM accumulate: per thread, 4 gate-columns of one hidden unit, one batch row.
// Per 4 k's: 1 conflict-free LDS.128 (x) + 4 broadcast LDS.128 (w) + 16 FFMA.
__device__ __forceinline__ void accum_chunk(const float* __restrict__ xs,
                                            const float* __restrict__ ws,
                                            int m, int ul, float4& acc) {
#pragma unroll
    for (int kq = 0; kq < KC / 4; ++kq) {
        float4 xv = *reinterpret_cast<const float4*>(xs + m * XST + kq * 4);
        const float* wb = ws + (kq * 4) * 16 + ul * 4;
        float xarr[4] = {xv.x, xv.y, xv.z, xv.w};
#pragma unroll
        for (int q = 0; q < 4; ++q) {
            float4 w = *reinterpret_cast<const float4*>(wb + q * 16);
            acc.x = fmaf(xarr[q], w.x, acc.x);
            acc.y = fmaf(xarr[q], w.y, acc.y);
            acc.z = fmaf(xarr[q], w.z, acc.z);
            acc.w = fmaf(xarr[q], w.w, acc.w);
        }
    }
}

// ---------------- init / reorder ----------------
__global__ void init_kernel() {
    int idx = blockIdx.x * blockDim.x + threadIdx.x;
    int stride = gridDim.x * blockDim.x;
    for (int i = idx; i < 2 * 64 * 512; i += stride) { g_h0[i] = 0.f; g_h1[i] = 0.f; }
    for (int i = idx; i < 64 * 512; i += stride) g_en_last[i] = 0.f;
    if (idx == 0) g_bar = 0u;
}

// Column permutation: newcol = ublk*16 + ul*4 + g  <-  origcol = g*512 + ublk*4 + ul
__global__ void reorder_kernel(const float* __restrict__ src, size_t dst_off, int K) {
    size_t n = (size_t)K * 2048;
    float* dst = g_Wr + dst_off;
    for (size_t idx = (size_t)blockIdx.x * blockDim.x + threadIdx.x; idx < n;
         idx += (size_t)gridDim.x * blockDim.x) {
        int k    = (int)(idx >> 11);
        int ncol = (int)(idx & 2047);
        int ublk = ncol >> 4;
        int r    = ncol & 15;
        dst[idx] = src[(size_t)k * 2048 + (size_t)(r & 3) * 512 + ublk * 4 + (r >> 2)];
    }
}

// ---------------- encoder (persistent, 256 steps, 1 grid barrier/step) ----------------
__global__ void __launch_bounds__(TPB, 1) encoder_kernel(
    const int* __restrict__ en_input, const int* __restrict__ en_len,
    const float* __restrict__ embed,
    const float* __restrict__ b0g, const float* __restrict__ b1g)
{
    const int cta = blockIdx.x, tid = threadIdx.x;
    const int m = tid & 63, ul = tid >> 6;
    const int unit = cta * 4 + ul;

    __shared__ __align__(16) float xs[64 * XST];
    __shared__ __align__(16) float ws[KC * 16];
    __shared__ int toks[64];
    __shared__ int lens[64];
    __shared__ float b0s[16], b1s[16];

    if (tid < 64) lens[tid] = en_len[tid];
    if (tid < 16) {
        b0s[tid] = b0g[(tid & 3) * 512 + cta * 4 + (tid >> 2)];
        b1s[tid] = b1g[(tid & 3) * 512 + cta * 4 + (tid >> 2)];
    }

    const float* W0 = g_Wr;
    const float* W1 = g_Wr + (size_t)768 * 2048;

    float c0 = 0.f, c1 = 0.f, h0r = 0.f, h1r = 0.f;

    for (int t = 0; t < 256; ++t) {
        const float* h0prev = g_h0 + ((t + 1) & 1) * (64 * 512);
        float*       h0cur  = g_h0 + (t & 1) * (64 * 512);
        const float* h1prev = g_h1 + ((t + 1) & 1) * (64 * 512);
        float*       h1cur  = g_h1 + (t & 1) * (64 * 512);

        if (tid < 64) toks[tid] = en_input[tid * 256 + t];

        // ---- layer 0: K = 768  (x = [emb(256) | h0_prev(512)]) ----
        float4 acc = make_float4(0.f, 0.f, 0.f, 0.f);
        for (int k0 = 0; k0 < 768; k0 += KC) {
            __syncthreads();
            for (int e = tid; e < 64 * KC; e += TPB) {
                int r = e >> 6, kk = e & 63;
                int k = k0 + kk;
                xs[r * XST + kk] = (k < 256) ? embed[toks[r] * 256 + k]
                                             : h0prev[r * 512 + (k - 256)];
            }
            for (int e = tid; e < KC * 4; e += TPB) {
                int kk = e >> 2, j4 = e & 3;
                reinterpret_cast<float4*>(ws)[kk * 4 + j4] =
                    reinterpret_cast<const float4*>(W0 + (size_t)(k0 + kk) * 2048 + cta * 16)[j4];
            }
            __syncthreads();
            accum_chunk(xs, ws, m, ul, acc);
        }
        {
            bool valid = t < lens[m];
            float zi = acc.x + b0s[ul * 4 + 0];
            float zj = acc.y + b0s[ul * 4 + 1];
            float zf = acc.z + b0s[ul * 4 + 2];
            float zo = acc.w + b0s[ul * 4 + 3];
            float nc = c0 * sigmoidf_(zf + 1.0f) + sigmoidf_(zi) * tanhf(zj);
            float nh = tanhf(nc) * sigmoidf_(zo);
            if (valid) { c0 = nc; h0r = nh; }
            h0cur[m * 512 + unit] = h0r;
        }
        grid_bar((unsigned)(t + 1) * NCTA);

        // ---- layer 1: K = 1024 (x = [h0_cur(512) | h1_prev(512)]) ----
        acc = make_float4(0.f, 0.f, 0.f, 0.f);
        for (int k0 = 0; k0 < 1024; k0 += KC) {
            __syncthreads();
            for (int e = tid; e < 64 * KC; e += TPB) {
                int r = e >> 6, kk = e & 63;
                int k = k0 + kk;
                xs[r * XST + kk] = (k < 512) ? h0cur[r * 512 + k]
                                             : h1prev[r * 512 + (k - 512)];
            }
            for (int e = tid; e < KC * 4; e += TPB) {
                int kk = e >> 2, j4 = e & 3;
                reinterpret_cast<float4*>(ws)[kk * 4 + j4] =
                    reinterpret_cast<const float4*>(W1 + (size_t)(k0 + kk) * 2048 + cta * 16)[j4];
            }
            __syncthreads();
            accum_chunk(xs, ws, m, ul, acc);
        }
        {
            bool valid = t < lens[m];
            float zi = acc.x + b1s[ul * 4 + 0];
            float zj = acc.y + b1s[ul * 4 + 1];
            float zf = acc.z + b1s[ul * 4 + 2];
            float zo = acc.w + b1s[ul * 4 + 3];
            float nc = c1 * sigmoidf_(zf + 1.0f) + sigmoidf_(zi) * tanhf(zj);
            float nh = tanhf(nc) * sigmoidf_(zo);
            if (valid) { c1 = nc; h1r = nh; g_en_last[m * 512 + unit] = nh; }
            h1cur[m * 512 + unit] = h1r;
        }
        // no trailing barrier needed: double-buffered h makes next step's phase-A safe
    }
    g_c0[m * 512 + unit] = c0;
    g_c1[m * 512 + unit] = c1;
}

// ---------------- decoder (persistent, 256 steps) ----------------
__global__ void __launch_bounds__(TPB, 1) decoder_kernel(
    const int* __restrict__ dec_input, const int* __restrict__ dec_len,
    const float* __restrict__ embed,
    const float* __restrict__ b0g, const float* __restrict__ b1g)
{
    const int cta = blockIdx.x, tid = threadIdx.x;
    const int m = tid & 63, ul = tid >> 6;
    const int unit = cta * 4 + ul;

    __shared__ __align__(16) float xs[64 * XST];
    __shared__ __align__(16) float ws[KC * 16];
    __shared__ int toks[64];
    __shared__ int lens[64];
    __shared__ float b0s[16], b1s[16];

    if (tid < 64) lens[tid] = dec_len[tid];
    if (tid < 16) {
        b0s[tid] = b0g[(tid & 3) * 512 + cta * 4 + (tid >> 2)];
        b1s[tid] = b1g[(tid & 3) * 512 + cta * 4 + (tid >> 2)];
    }

    const float* W0 = g_Wr + (size_t)1792 * 2048;  // decW0 [1280][2048]
    const float* W1 = g_Wr + (size_t)3072 * 2048;  // decW1 [1024][2048]

    // initial state = encoder final state
    float c0 = g_c0[m * 512 + unit];
    float c1 = g_c1[m * 512 + unit];
    float h0r = g_h0[1 * (64 * 512) + m * 512 + unit];  // encoder t=255 wrote buffer 1
    float h1r = g_h1[1 * (64 * 512) + m * 512 + unit];

    for (int t = 0; t < 256; ++t) {
        const float* h0prev = g_h0 + ((t + 1) & 1) * (64 * 512);
        float*       h0cur  = g_h0 + (t & 1) * (64 * 512);
        const float* h1prev = g_h1 + ((t + 1) & 1) * (64 * 512);
        float*       h1cur  = g_h1 + (t & 1) * (64 * 512);

        if (tid < 64) toks[tid] = dec_input[tid * 256 + t];

        // ---- layer 0: K = 1280 (x = [emb(256) | en_last(512) | h0_prev(512)]) ----
        float4 acc = make_float4(0.f, 0.f, 0.f, 0.f);
        for (int k0 = 0; k0 < 1280; k0 += KC) {
            __syncthreads();
            for (int e = tid; e < 64 * KC; e += TPB) {
                int r = e >> 6, kk = e & 63;
                int k = k0 + kk;
                float v;
                if (k < 256)      v = embed[toks[r] * 256 + k];
                else if (k < 768) v = g_en_last[r * 512 + (k - 256)];
                else              v = h0prev[r * 512 + (k - 768)];
                xs[r * XST + kk] = v;
            }
            for (int e = tid; e < KC * 4; e += TPB) {
                int kk = e >> 2, j4 = e & 3;
                reinterpret_cast<float4*>(ws)[kk * 4 + j4] =
                    reinterpret_cast<const float4*>(W0 + (size_t)(k0 + kk) * 2048 + cta * 16)[j4];
            }
            __syncthreads();
            accum_chunk(xs, ws, m, ul, acc);
        }
        {
            bool valid = t < lens[m];
            float zi = acc.x + b0s[ul * 4 + 0];
            float zj = acc.y + b0s[ul * 4 + 1];
            float zf = acc.z + b0s[ul * 4 + 2];
            float zo = acc.w + b0s[ul * 4 + 3];
            float nc = c0 * sigmoidf_(zf + 1.0f) + sigmoidf_(zi) * tanhf(zj);
            float nh = tanhf(nc) * sigmoidf_(zo);
            if (valid) { c0 = nc; h0r = nh; }
            h0cur[m * 512 + unit] = h0r;
        }
        grid_bar((unsigned)(256 + t + 1) * NCTA);

        // ---- layer 1: K = 1024 ----
        acc = make_float4(0.f, 0.f, 0.f, 0.f);
        for (int k0 = 0; k0 < 1024; k0 += KC) {
            __syncthreads();
            for (int e = tid; e < 64 * KC; e += TPB) {
                int r = e >> 6, kk = e & 63;
                int k = k0 + kk;
                xs[r * XST + kk] = (k < 512) ? h0cur[r * 512 + k]
                                             : h1prev[r * 512 + (k - 512)];
            }
            for (int e = tid; e < KC * 4; e += TPB) {
                int kk = e >> 2, j4 = e & 3;
                reinterpret_cast<float4*>(ws)[kk * 4 + j4] =
                    reinterpret_cast<const float4*>(W1 + (size_t)(k0 + kk) * 2048 + cta * 16)[j4];
            }
            __syncthreads();
            accum_chunk(xs, ws, m, ul, acc);
        }
        {
            bool valid = t < lens[m];
            float zi = acc.x + b1s[ul * 4 + 0];
            float zj = acc.y + b1s[ul * 4 + 1];
            float zf = acc.z + b1s[ul * 4 + 2];
            float zo = acc.w + b1s[ul * 4 + 3];
            float nc = c1 * sigmoidf_(zf + 1.0f) + sigmoidf_(zi) * tanhf(zj);
            float nh = tanhf(nc) * sigmoidf_(zo);
            if (valid) { c1 = nc; h1r = nh; }
            h1cur[m * 512 + unit] = h1r;
            g_dec_out[((size_t)m * 256 + t) * 512 + unit] = valid ? h1r : 0.f;
        }
    }
}

// ---------------- projection: [16384,512] @ [512,128] + bias ----------------
__global__ void __launch_bounds__(TPB, 1) proj_kernel(
    const float* __restrict__ projW, const float* __restrict__ projb,
    float* __restrict__ out)
{
    const int row0 = blockIdx.x * 128;
    __shared__ __align__(16) float As[128][33];
    __shared__ __align__(16) float Ws[32][128];
    const int tid = threadIdx.x;
    const int tc = tid & 31, rg = tid >> 5;

    float4 acc[16];
#pragma unroll
    for (int i = 0; i < 16; i++) acc[i] = make_float4(0.f, 0.f, 0.f, 0.f);

    for (int k0 = 0; k0 < 512; k0 += 32) {
        for (int e = tid; e < 128 * 32; e += TPB) {
            int r = e >> 5, kk = e & 31;
            As[r][kk] = g_dec_out[(size_t)(row0 + r) * 512 + k0 + kk];
        }
        for (int e = tid; e < 32 * 128; e += TPB) {
            int kk = e >> 7, c = e & 127;
            Ws[kk][c] = projW[(size_t)(k0 + kk) * 128 + c];
        }
        __syncthreads();
#pragma unroll
        for (int kk = 0; kk < 32; kk++) {
            float4 w = *reinterpret_cast<const float4*>(&Ws[kk][tc * 4]);
#pragma unroll
            for (int r = 0; r < 16; r++) {
                float a = As[rg * 16 + r][kk];
                acc[r].x = fmaf(a, w.x, acc[r].x);
                acc[r].y = fmaf(a, w.y, acc[r].y);
                acc[r].z = fmaf(a, w.z, acc[r].z);
                acc[r].w = fmaf(a, w.w, acc[r].w);
            }
        }
        __syncthreads();
    }
    float4 pb = *reinterpret_cast<const float4*>(&projb[tc * 4]);
#pragma unroll
    for (int r = 0; r < 16; r++) {
        int row = row0 + rg * 16 + r;
        float4 v = make_float4(acc[r].x + pb.x, acc[r].y + pb.y,
                               acc[r].z + pb.z, acc[r].w + pb.w);
        *reinterpret_cast<float4*>(&out[(size_t)row * 128 + tc * 4]) = v;
    }
}

// ---------------- launch ----------------
extern "C" void kernel_launch(void* const* d_in, const int* in_sizes, int n_in,
                              void* d_out, int out_size) {
    const int*   en_input  = (const int*)d_in[0];
    const int*   en_len    = (const int*)d_in[1];
    const int*   dec_input = (const int*)d_in[2];
    const int*   dec_len   = (const int*)d_in[3];
    const float* embed     = (const float*)d_in[4];
    const float* encW0     = (const float*)d_in[5];
    const float* encb0     = (const float*)d_in[6];
    const float* encW1     = (const float*)d_in[7];
    const float* encb1     = (const float*)d_in[8];
    const float* decW0     = (const float*)d_in[9];
    const float* decb0     = (const float*)d_in[10];
    const float* decW1     = (const float*)d_in[11];
    const float* decb1     = (const float*)d_in[12];
    const float* projW     = (const float*)d_in[13];
    const float* projb     = (const float*)d_in[14];
    float* out = (float*)d_out;

    init_kernel<<<128, 256>>>();
    reorder_kernel<<<512, 256>>>(encW0, (size_t)0,           768);
    reorder_kernel<<<512, 256>>>(encW1, (size_t)768  * 2048, 1024);
    reorder_kernel<<<512, 256>>>(decW0, (size_t)1792 * 2048, 1280);
    reorder_kernel<<<512, 256>>>(decW1, (size_t)3072 * 2048, 1024);
    encoder_kernel<<<NCTA, TPB>>>(en_input, en_len, embed, encb0, encb1);
    decoder_kernel<<<NCTA, TPB>>>(dec_input, dec_len, embed, decb0, decb1);
    proj_kernel<<<128, TPB>>>(projW, projb, out);
}

// round 3
// speedup vs baseline: 2.3166x; 2.3166x over previous
#include <cuda_runtime.h>
#include <math.h>

#define NCTA 128
#define TPB  256
#define XSTF 68              // floats per xs row (17 float4s, odd*16B -> conflict-free)
#define XBUF (64 * XSTF)     // floats per xs buffer

// ---------------- device scratch ----------------
__device__ float g_Wr[4096 * 2048];     // reordered, CTA-major slabs
__device__ float g_h0[2 * 64 * 512];
__device__ float g_h1[2 * 64 * 512];
__device__ float g_c0[64 * 512];
__device__ float g_c1[64 * 512];
__device__ float g_en_last[64 * 512];
__device__ float g_dec_out[64 * 256 * 512];
__device__ unsigned g_bar;

__device__ __forceinline__ float sigmoidf_(float x) { return 1.0f / (1.0f + __expf(-x)); }

__device__ __forceinline__ void grid_bar(unsigned target) {
    __syncthreads();
    if (threadIdx.x == 0) {
        __threadfence();
        atomicAdd(&g_bar, 1u);
        unsigned v;
        do {
            asm volatile("ld.acquire.gpu.u32 %0, [%1];" : "=r"(v) : "l"(&g_bar));
        } while (v < target);
    }
    __syncthreads();
}

// 64 k's: per thread 16 LDS.128 x + 64 LDS.128 w (broadcast) + 256 FFMA
__device__ __forceinline__ void compute_chunk(const float* __restrict__ xrow,
                                              const float4* __restrict__ wbase,
                                              float4& acc) {
#pragma unroll
    for (int kq = 0; kq < 16; ++kq) {
        float4 xv = reinterpret_cast<const float4*>(xrow)[kq];
        float xa[4] = {xv.x, xv.y, xv.z, xv.w};
#pragma unroll
        for (int q = 0; q < 4; ++q) {
            float4 w = wbase[(kq * 4 + q) * 4];
            acc.x = fmaf(xa[q], w.x, acc.x);
            acc.y = fmaf(xa[q], w.y, acc.y);
            acc.z = fmaf(xa[q], w.z, acc.z);
            acc.w = fmaf(xa[q], w.w, acc.w);
        }
    }
}

// ---------------- init / reorder ----------------
__global__ void init_kernel() {
    int idx = blockIdx.x * blockDim.x + threadIdx.x;
    int stride = gridDim.x * blockDim.x;
    for (int i = idx; i < 2 * 64 * 512; i += stride) { g_h0[i] = 0.f; g_h1[i] = 0.f; }
    if (idx == 0) g_bar = 0u;
}

// dst layout: [ublk][k][16] contiguous per-CTA slab; r = ul*4+g
__global__ void reorder_kernel(const float* __restrict__ src, size_t dst_off, int K) {
    size_t n = (size_t)K * 2048;
    float* dst = g_Wr + dst_off;
    int slab = K * 16;
    for (size_t idx = (size_t)blockIdx.x * blockDim.x + threadIdx.x; idx < n;
         idx += (size_t)gridDim.x * blockDim.x) {
        int ublk = (int)(idx / slab);
        int rem  = (int)(idx - (size_t)ublk * slab);
        int k = rem >> 4;
        int r = rem & 15;
        dst[idx] = src[(size_t)k * 2048 + (size_t)(r & 3) * 512 + ublk * 4 + (r >> 2)];
    }
}

// ---------------- encoder ----------------
__global__ void __launch_bounds__(TPB, 1) encoder_kernel(
    const int* __restrict__ en_input, const int* __restrict__ en_len,
    const float* __restrict__ embed,
    const float* __restrict__ b0g, const float* __restrict__ b1g)
{
    extern __shared__ float sm[];
    float* ws0 = sm;                         // 768*16
    float* ws1 = sm + 768 * 16;              // 1024*16
    float* xs  = sm + 768 * 16 + 1024 * 16;  // 2 * XBUF
    __shared__ int lens[64];
    __shared__ float b0s[16], b1s[16];

    const int cta = blockIdx.x, tid = threadIdx.x;
    const int m = tid >> 2, ul = tid & 3;
    const int unit = cta * 4 + ul;
    const int fr0 = tid >> 4, fkq = tid & 15;

    if (tid < 64) lens[tid] = en_len[tid];
    if (tid < 16) {
        b0s[tid] = b0g[(tid & 3) * 512 + cta * 4 + (tid >> 2)];
        b1s[tid] = b1g[(tid & 3) * 512 + cta * 4 + (tid >> 2)];
    }
    // preload weights into smem (once)
    {
        const float4* w0g = (const float4*)(g_Wr + (size_t)cta * (768 * 16));
        float4* s0 = (float4*)ws0;
        for (int i = tid; i < 768 * 4; i += TPB) s0[i] = w0g[i];
        const float4* w1g = (const float4*)(g_Wr + (size_t)768 * 2048 + (size_t)cta * (1024 * 16));
        float4* s1 = (float4*)ws1;
        for (int i = tid; i < 1024 * 4; i += TPB) s1[i] = w1g[i];
    }
    __syncthreads();

    const float4* w0f4 = (const float4*)ws0;
    const float4* w1f4 = (const float4*)ws1;

    float c0 = 0.f, c1 = 0.f, h0r = 0.f, h1r = 0.f;

    for (int t = 0; t < 256; ++t) {
        const float* h0prev = g_h0 + ((t + 1) & 1) * (64 * 512);
        float*       h0cur  = g_h0 + (t & 1) * (64 * 512);
        const float* h1prev = g_h1 + ((t + 1) & 1) * (64 * 512);
        float*       h1cur  = g_h1 + (t & 1) * (64 * 512);

        // ---- layer 0: K = 768, 12 chunks (x = [emb(256) | h0_prev(512)]) ----
        float4 acc = make_float4(0.f, 0.f, 0.f, 0.f);
        {
            float4 pre[4];
            // prologue fill chunk0 (embed)
#pragma unroll
            for (int i = 0; i < 4; ++i) {
                int r = fr0 + 16 * i;
                int tok = en_input[r * 256 + t];
                pre[i] = reinterpret_cast<const float4*>(embed + (size_t)tok * 256)[fkq];
            }
#pragma unroll
            for (int i = 0; i < 4; ++i)
                reinterpret_cast<float4*>(xs + (fr0 + 16 * i) * XSTF)[fkq] = pre[i];
            int buf = 0;
            for (int ch = 0; ch < 12; ++ch) {
                float4 nxt[4];
                if (ch + 1 < 12) {
                    int cn = ch + 1;
                    if (cn < 4) {
#pragma unroll
                        for (int i = 0; i < 4; ++i) {
                            int r = fr0 + 16 * i;
                            int tok = en_input[r * 256 + t];
                            nxt[i] = reinterpret_cast<const float4*>(embed + (size_t)tok * 256 + cn * 64)[fkq];
                        }
                    } else {
                        const float* hp = h0prev + (cn * 64 - 256);
#pragma unroll
                        for (int i = 0; i < 4; ++i)
                            nxt[i] = __ldcg(reinterpret_cast<const float4*>(hp + (fr0 + 16 * i) * 512) + fkq);
                    }
                }
                __syncthreads();
                compute_chunk(xs + buf * XBUF + m * XSTF, w0f4 + ch * 256 + ul, acc);
                if (ch + 1 < 12) {
                    float* xb = xs + (buf ^ 1) * XBUF;
#pragma unroll
                    for (int i = 0; i < 4; ++i)
                        reinterpret_cast<float4*>(xb + (fr0 + 16 * i) * XSTF)[fkq] = nxt[i];
                }
                buf ^= 1;
            }
        }
        {
            bool valid = t < lens[m];
            float zi = acc.x + b0s[ul * 4 + 0];
            float zj = acc.y + b0s[ul * 4 + 1];
            float zf = acc.z + b0s[ul * 4 + 2];
            float zo = acc.w + b0s[ul * 4 + 3];
            float nc = c0 * sigmoidf_(zf + 1.0f) + sigmoidf_(zi) * tanhf(zj);
            float nh = tanhf(nc) * sigmoidf_(zo);
            if (valid) { c0 = nc; h0r = nh; }
            h0cur[m * 512 + unit] = h0r;
        }
        grid_bar((unsigned)(t + 1) * NCTA);

        // ---- layer 1: K = 1024, 16 chunks (x = [h0_cur | h1_prev]) ----
        acc = make_float4(0.f, 0.f, 0.f, 0.f);
        {
            float4 pre[4];
#pragma unroll
            for (int i = 0; i < 4; ++i)
                pre[i] = __ldcg(reinterpret_cast<const float4*>(h0cur + (fr0 + 16 * i) * 512) + fkq);
#pragma unroll
            for (int i = 0; i < 4; ++i)
                reinterpret_cast<float4*>(xs + (fr0 + 16 * i) * XSTF)[fkq] = pre[i];
            int buf = 0;
            for (int ch = 0; ch < 16; ++ch) {
                float4 nxt[4];
                if (ch + 1 < 16) {
                    int cn = ch + 1;
                    const float* hp = (cn < 8) ? (h0cur + cn * 64) : (h1prev + (cn * 64 - 512));
#pragma unroll
                    for (int i = 0; i < 4; ++i)
                        nxt[i] = __ldcg(reinterpret_cast<const float4*>(hp + (fr0 + 16 * i) * 512) + fkq);
                }
                __syncthreads();
                compute_chunk(xs + buf * XBUF + m * XSTF, w1f4 + ch * 256 + ul, acc);
                if (ch + 1 < 16) {
                    float* xb = xs + (buf ^ 1) * XBUF;
#pragma unroll
                    for (int i = 0; i < 4; ++i)
                        reinterpret_cast<float4*>(xb + (fr0 + 16 * i) * XSTF)[fkq] = nxt[i];
                }
                buf ^= 1;
            }
        }
        __syncthreads();   // protect xs before next step's prologue STS
        {
            bool valid = t < lens[m];
            float zi = acc.x + b1s[ul * 4 + 0];
            float zj = acc.y + b1s[ul * 4 + 1];
            float zf = acc.z + b1s[ul * 4 + 2];
            float zo = acc.w + b1s[ul * 4 + 3];
            float nc = c1 * sigmoidf_(zf + 1.0f) + sigmoidf_(zi) * tanhf(zj);
            float nh = tanhf(nc) * sigmoidf_(zo);
            if (valid) { c1 = nc; h1r = nh; g_en_last[m * 512 + unit] = nh; }
            h1cur[m * 512 + unit] = h1r;
        }
    }
    g_c0[m * 512 + unit] = c0;
    g_c1[m * 512 + unit] = c1;
}

// ---------------- decoder ----------------
__global__ void __launch_bounds__(TPB, 1) decoder_kernel(
    const int* __restrict__ dec_input, const int* __restrict__ dec_len,
    const float* __restrict__ embed,
    const float* __restrict__ b0g, const float* __restrict__ b1g)
{
    extern __shared__ float sm[];
    float* ws0 = sm;                          // 1280*16
    float* ws1 = sm + 1280 * 16;              // 1024*16
    float* xs  = sm + 1280 * 16 + 1024 * 16;  // 2 * XBUF
    __shared__ int lens[64];
    __shared__ float b0s[16], b1s[16];

    const int cta = blockIdx.x, tid = threadIdx.x;
    const int m = tid >> 2, ul = tid & 3;
    const int unit = cta * 4 + ul;
    const int fr0 = tid >> 4, fkq = tid & 15;

    if (tid < 64) lens[tid] = dec_len[tid];
    if (tid < 16) {
        b0s[tid] = b0g[(tid & 3) * 512 + cta * 4 + (tid >> 2)];
        b1s[tid] = b1g[(tid & 3) * 512 + cta * 4 + (tid >> 2)];
    }
    {
        const float4* w0g = (const float4*)(g_Wr + (size_t)1792 * 2048 + (size_t)cta * (1280 * 16));
        float4* s0 = (float4*)ws0;
        for (int i = tid; i < 1280 * 4; i += TPB) s0[i] = w0g[i];
        const float4* w1g = (const float4*)(g_Wr + (size_t)3072 * 2048 + (size_t)cta * (1024 * 16));
        float4* s1 = (float4*)ws1;
        for (int i = tid; i < 1024 * 4; i += TPB) s1[i] = w1g[i];
    }
    __syncthreads();

    const float4* w0f4 = (const float4*)ws0;
    const float4* w1f4 = (const float4*)ws1;

    float c0 = g_c0[m * 512 + unit];
    float c1 = g_c1[m * 512 + unit];
    float h0r = g_h0[64 * 512 + m * 512 + unit];   // encoder t=255 wrote buffer 1
    float h1r = g_h1[64 * 512 + m * 512 + unit];

    for (int t = 0; t < 256; ++t) {
        const float* h0prev = g_h0 + ((t + 1) & 1) * (64 * 512);
        float*       h0cur  = g_h0 + (t & 1) * (64 * 512);
        const float* h1prev = g_h1 + ((t + 1) & 1) * (64 * 512);
        float*       h1cur  = g_h1 + (t & 1) * (64 * 512);

        // ---- layer 0: K = 1280, 20 chunks (x = [emb | en_last | h0_prev]) ----
        float4 acc = make_float4(0.f, 0.f, 0.f, 0.f);
        {
            float4 pre[4];
#pragma unroll
            for (int i = 0; i < 4; ++i) {
                int r = fr0 + 16 * i;
                int tok = dec_input[r * 256 + t];
                pre[i] = reinterpret_cast<const float4*>(embed + (size_t)tok * 256)[fkq];
            }
#pragma unroll
            for (int i = 0; i < 4; ++i)
                reinterpret_cast<float4*>(xs + (fr0 + 16 * i) * XSTF)[fkq] = pre[i];
            int buf = 0;
            for (int ch = 0; ch < 20; ++ch) {
                float4 nxt[4];
                if (ch + 1 < 20) {
                    int cn = ch + 1;
                    if (cn < 4) {
#pragma unroll
                        for (int i = 0; i < 4; ++i) {
                            int r = fr0 + 16 * i;
                            int tok = dec_input[r * 256 + t];
                            nxt[i] = reinterpret_cast<const float4*>(embed + (size_t)tok * 256 + cn * 64)[fkq];
                        }
                    } else if (cn < 12) {
                        const float* sp = g_en_last + (cn * 64 - 256);
#pragma unroll
                        for (int i = 0; i < 4; ++i)
                            nxt[i] = reinterpret_cast<const float4*>(sp + (fr0 + 16 * i) * 512)[fkq];
                    } else {
                        const float* hp = h0prev + (cn * 64 - 768);
#pragma unroll
                        for (int i = 0; i < 4; ++i)
                            nxt[i] = __ldcg(reinterpret_cast<const float4*>(hp + (fr0 + 16 * i) * 512) + fkq);
                    }
                }
                __syncthreads();
                compute_chunk(xs + buf * XBUF + m * XSTF, w0f4 + ch * 256 + ul, acc);
                if (ch + 1 < 20) {
                    float* xb = xs + (buf ^ 1) * XBUF;
#pragma unroll
                    for (int i = 0; i < 4; ++i)
                        reinterpret_cast<float4*>(xb + (fr0 + 16 * i) * XSTF)[fkq] = nxt[i];
                }
                buf ^= 1;
            }
        }
        {
            bool valid = t < lens[m];
            float zi = acc.x + b0s[ul * 4 + 0];
            float zj = acc.y + b0s[ul * 4 + 1];
            float zf = acc.z + b0s[ul * 4 + 2];
            float zo = acc.w + b0s[ul * 4 + 3];
            float nc = c0 * sigmoidf_(zf + 1.0f) + sigmoidf_(zi) * tanhf(zj);
            float nh = tanhf(nc) * sigmoidf_(zo);
            if (valid) { c0 = nc; h0r = nh; }
            h0cur[m * 512 + unit] = h0r;
        }
        grid_bar((unsigned)(256 + t + 1) * NCTA);

        // ---- layer 1: K = 1024, 16 chunks ----
        acc = make_float4(0.f, 0.f, 0.f, 0.f);
        {
            float4 pre[4];
#pragma unroll
            for (int i = 0; i < 4; ++i)
                pre[i] = __ldcg(reinterpret_cast<const float4*>(h0cur + (fr0 + 16 * i) * 512) + fkq);
#pragma unroll
            for (int i = 0; i < 4; ++i)
                reinterpret_cast<float4*>(xs + (fr0 + 16 * i) * XSTF)[fkq] = pre[i];
            int buf = 0;
            for (int ch = 0; ch < 16; ++ch) {
                float4 nxt[4];
                if (ch + 1 < 16) {
                    int cn = ch + 1;
                    const float* hp = (cn < 8) ? (h0cur + cn * 64) : (h1prev + (cn * 64 - 512));
#pragma unroll
                    for (int i = 0; i < 4; ++i)
                        nxt[i] = __ldcg(reinterpret_cast<const float4*>(hp + (fr0 + 16 * i) * 512) + fkq);
                }
                __syncthreads();
                compute_chunk(xs + buf * XBUF + m * XSTF, w1f4 + ch * 256 + ul, acc);
                if (ch + 1 < 16) {
                    float* xb = xs + (buf ^ 1) * XBUF;
#pragma unroll
                    for (int i = 0; i < 4; ++i)
                        reinterpret_cast<float4*>(xb + (fr0 + 16 * i) * XSTF)[fkq] = nxt[i];
                }
                buf ^= 1;
            }
        }
        __syncthreads();
        {
            bool valid = t < lens[m];
            float zi = acc.x + b1s[ul * 4 + 0];
            float zj = acc.y + b1s[ul * 4 + 1];
            float zf = acc.z + b1s[ul * 4 + 2];
            float zo = acc.w + b1s[ul * 4 + 3];
            float nc = c1 * sigmoidf_(zf + 1.0f) + sigmoidf_(zi) * tanhf(zj);
            float nh = tanhf(nc) * sigmoidf_(zo);
            if (valid) { c1 = nc; h1r = nh; }
            h1cur[m * 512 + unit] = h1r;
            g_dec_out[((size_t)m * 256 + t) * 512 + unit] = valid ? h1r : 0.f;
        }
    }
}

// ---------------- projection: [16384,512] @ [512,128] + bias ----------------
__global__ void __launch_bounds__(TPB, 1) proj_kernel(
    const float* __restrict__ projW, const float* __restrict__ projb,
    float* __restrict__ out)
{
    const int row0 = blockIdx.x * 128;
    __shared__ __align__(16) float As[128][33];
    __shared__ __align__(16) float Ws[32][128];
    const int tid = threadIdx.x;
    const int tc = tid & 31, rg = tid >> 5;

    float4 acc[16];
#pragma unroll
    for (int i = 0; i < 16; i++) acc[i] = make_float4(0.f, 0.f, 0.f, 0.f);

    for (int k0 = 0; k0 < 512; k0 += 32) {
        for (int e = tid; e < 128 * 32; e += TPB) {
            int r = e >> 5, kk = e & 31;
            As[r][kk] = g_dec_out[(size_t)(row0 + r) * 512 + k0 + kk];
        }
        for (int e = tid; e < 32 * 128; e += TPB) {
            int kk = e >> 7, c = e & 127;
            Ws[kk][c] = projW[(size_t)(k0 + kk) * 128 + c];
        }
        __syncthreads();
#pragma unroll
        for (int kk = 0; kk < 32; kk++) {
            float4 w = *reinterpret_cast<const float4*>(&Ws[kk][tc * 4]);
#pragma unroll
            for (int r = 0; r < 16; r++) {
                float a = As[rg * 16 + r][kk];
                acc[r].x = fmaf(a, w.x, acc[r].x);
                acc[r].y = fmaf(a, w.y, acc[r].y);
                acc[r].z = fmaf(a, w.z, acc[r].z);
                acc[r].w = fmaf(a, w.w, acc[r].w);
            }
        }
        __syncthreads();
    }
    float4 pb = *reinterpret_cast<const float4*>(&projb[tc * 4]);
#pragma unroll
    for (int r = 0; r < 16; r++) {
        int row = row0 + rg * 16 + r;
        float4 v = make_float4(acc[r].x + pb.x, acc[r].y + pb.y,
                               acc[r].z + pb.z, acc[r].w + pb.w);
        *reinterpret_cast<float4*>(&out[(size_t)row * 128 + tc * 4]) = v;
    }
}

// ---------------- launch ----------------
#define ENC_SMEM ((768*16 + 1024*16 + 2*XBUF) * 4)
#define DEC_SMEM ((1280*16 + 1024*16 + 2*XBUF) * 4)

extern "C" void kernel_launch(void* const* d_in, const int* in_sizes, int n_in,
                              void* d_out, int out_size) {
    const int*   en_input  = (const int*)d_in[0];
    const int*   en_len    = (const int*)d_in[1];
    const int*   dec_input = (const int*)d_in[2];
    const int*   dec_len   = (const int*)d_in[3];
    const float* embed     = (const float*)d_in[4];
    const float* encW0     = (const float*)d_in[5];
    const float* encb0     = (const float*)d_in[6];
    const float* encW1     = (const float*)d_in[7];
    const float* encb1     = (const float*)d_in[8];
    const float* decW0     = (const float*)d_in[9];
    const float* decb0     = (const float*)d_in[10];
    const float* decW1     = (const float*)d_in[11];
    const float* decb1     = (const float*)d_in[12];
    const float* projW     = (const float*)d_in[13];
    const float* projb     = (const float*)d_in[14];
    float* out = (float*)d_out;

    cudaFuncSetAttribute(encoder_kernel, cudaFuncAttributeMaxDynamicSharedMemorySize, ENC_SMEM);
    cudaFuncSetAttribute(decoder_kernel, cudaFuncAttributeMaxDynamicSharedMemorySize, DEC_SMEM);

    init_kernel<<<128, 256>>>();
    reorder_kernel<<<512, 256>>>(encW0, (size_t)0,           768);
    reorder_kernel<<<512, 256>>>(encW1, (size_t)768  * 2048, 1024);
    reorder_kernel<<<512, 256>>>(decW0, (size_t)1792 * 2048, 1280);
    reorder_kernel<<<512, 256>>>(decW1, (size_t)3072 * 2048, 1024);
    encoder_kernel<<<NCTA, TPB, ENC_SMEM>>>(en_input, en_len, embed, encb0, encb1);
    decoder_kernel<<<NCTA, TPB, DEC_SMEM>>>(dec_input, dec_len, embed, decb0, decb1);
    proj_kernel<<<128, TPB>>>(projW, projb, out);
}